// round 16
// baseline (speedup 1.0000x reference)
#include <cuda_runtime.h>
#include <cstdint>
#include <math.h>

// Problem shapes (fixed by the reference)
#define NB 8192          // batch
#define SS 10            // senses
#define HH 1024          // hidden
#define THREADS 256
#define NBLOCKS 148      // 1 block/SM (smem-bound); ~55 rows each via tickets
#define ALPHA_ROWS 16200 // 2700*6
#define ALPHA_CHUNKS 64
#define ALPHA_CHUNK 254  // 64*254 = 16256 >= 16200

#define SENT_BYTES 4096                         // 1024 f32
#define GLOSS_BYTES 40960                       // 10 x 1024 f32
#define ROW_BYTES (SENT_BYTES + GLOSS_BYTES)    // 45056
#define NBUF 4
#define CTRL_BYTES 1024
#define DYN_SMEM (NBUF * ROW_BYTES + CTRL_BYTES)   // 181248

// Scratch (device globals: no allocation allowed anywhere)
__device__ float g_margin_part[NB];
__device__ float g_alpha_part[ALPHA_CHUNKS];
__device__ unsigned int g_ticket;  // zero-init; self-resetting
__device__ unsigned int g_done;    // zero-init; self-resetting

__device__ __forceinline__ unsigned int smem_u32(const void* p) {
    return (unsigned int)__cvta_generic_to_shared(p);
}
__device__ __forceinline__ void mbar_init(unsigned int mbar, unsigned int cnt) {
    asm volatile("mbarrier.init.shared.b64 [%0], %1;" :: "r"(mbar), "r"(cnt) : "memory");
}
__device__ __forceinline__ void mbar_expect_tx(unsigned int mbar, unsigned int bytes) {
    asm volatile("mbarrier.arrive.expect_tx.shared.b64 _, [%0], %1;"
                 :: "r"(mbar), "r"(bytes) : "memory");
}
__device__ __forceinline__ void mbar_wait(unsigned int mbar, unsigned int parity) {
    asm volatile(
        "{\n\t"
        ".reg .pred P1;\n\t"
        "WAIT_LOOP_%=:\n\t"
        "mbarrier.try_wait.parity.acquire.cta.shared::cta.b64 P1, [%0], %1, 0x989680;\n\t"
        "@P1 bra.uni WAIT_DONE_%=;\n\t"
        "bra.uni WAIT_LOOP_%=;\n\t"
        "WAIT_DONE_%=:\n\t"
        "}"
        :: "r"(mbar), "r"(parity) : "memory");
}
// Non-tensor 1D bulk copy (TMA engine path) gmem -> smem.
__device__ __forceinline__ void bulk_g2s(unsigned int dst_smem, const void* src,
                                         unsigned int bytes, unsigned int mbar) {
    asm volatile(
        "cp.async.bulk.shared::cluster.global.mbarrier::complete_tx::bytes "
        "[%0], [%1], %2, [%3];"
        :: "r"(dst_smem), "l"(src), "r"(bytes), "r"(mbar) : "memory");
}

__global__ __launch_bounds__(THREADS)
void marginal_loss_fused(const float* __restrict__ sentence,
                         const float* __restrict__ gloss,
                         const float* __restrict__ alpha,
                         const int*   __restrict__ mask,
                         const int*   __restrict__ sids,
                         float* __restrict__ out, int out_size)
{
    extern __shared__ __align__(128) unsigned char smem[];
    unsigned char* ctrl = smem + NBUF * ROW_BYTES;
    // ctrl: [0:32) mbar[4], [32:48) tq[4], [48:64) sid[4],
    //       [64:224) mask[4][10], [224:544) red[10][8], [544:548) last
    unsigned long long* mbar_p = reinterpret_cast<unsigned long long*>(ctrl);
    unsigned int* s_tq  = reinterpret_cast<unsigned int*>(ctrl + 32);
    int*   s_sid  = reinterpret_cast<int*>(ctrl + 48);
    int*   s_mask = reinterpret_cast<int*>(ctrl + 64);
    float* s_red  = reinterpret_cast<float*>(ctrl + 224);
    int*   s_last = reinterpret_cast<int*>(ctrl + 544);

    const int tid  = threadIdx.x;
    const int lane = tid & 31;
    const int wid  = tid >> 5;

    if (tid < NBUF) mbar_init(smem_u32(&mbar_p[tid]), 1);
    __syncthreads();

    // ---- alpha prologue on blocks 0..63 ----
    if (blockIdx.x < ALPHA_CHUNKS) {
        const int c     = blockIdx.x;
        const int start = c * ALPHA_CHUNK;
        const int end   = min(start + ALPHA_CHUNK, ALPHA_ROWS);
        float part = 0.0f;
        for (int r = start + tid; r < end; r += THREADS) {
            const float* __restrict__ row = alpha + (size_t)r * 10;
            float s0 = 0.0f, mx = -1e30f;
            #pragma unroll
            for (int k = 0; k < 10; ++k) {
                float v = row[k];
                s0 += v;
                mx = fmaxf(mx, v);
            }
            part += (s0 == 0.0f) ? 0.0f : fabsf(mx - 1.0f);  // row_sum==0 -> 0
        }
        #pragma unroll
        for (int off = 16; off > 0; off >>= 1)
            part += __shfl_xor_sync(0xffffffffu, part, off);
        if (lane == 0) s_red[wid] = part;
        __syncthreads();
        if (tid == 0) {
            float tot = 0.0f;
            #pragma unroll
            for (int w = 0; w < 8; ++w) tot += s_red[w];
            g_alpha_part[c] = tot;
        }
        __syncthreads();
    }

    // ---- prime: 4 tickets, 4 outstanding whole-row TMA copies ----
    #pragma unroll
    for (int k = 0; k < NBUF; ++k) {
        if (tid == 0) s_tq[k] = atomicAdd(&g_ticket, 1u);
        __syncthreads();
        const unsigned int tt = s_tq[k];
        if (tt < NB) {
            unsigned char* buf = smem + k * ROW_BYTES;
            if (tid == 0) {
                const unsigned int mb = smem_u32(&mbar_p[k]);
                mbar_expect_tx(mb, ROW_BYTES);
                bulk_g2s(smem_u32(buf), sentence + (size_t)tt * HH, SENT_BYTES, mb);
                bulk_g2s(smem_u32(buf) + SENT_BYTES, gloss + (size_t)tt * SS * HH,
                         GLOSS_BYTES, mb);
            }
            if (tid < SS) s_mask[k * SS + tid] = mask[tt * SS + tid];
            if (tid == SS) s_sid[k] = sids[tt];
        }
        __syncthreads();
    }

    int s = 0;
    int ph[NBUF] = {0, 0, 0, 0};

    for (;;) {
        const unsigned int tt = s_tq[s];
        if (tt >= NB) break;   // monotone tickets: all newer slots also >= NB

        mbar_wait(smem_u32(&mbar_p[s]), ph[s]);
        ph[s] ^= 1;

        const float* bufp = reinterpret_cast<const float*>(smem + s * ROW_BYTES);
        const float4* sv4 = reinterpret_cast<const float4*>(bufp);
        const float4* gl4 = reinterpret_cast<const float4*>(bufp + HH);

        const float4 sv = sv4[tid];   // 256 float4 covers the whole row
        float acc[SS];
        #pragma unroll
        for (int q = 0; q < SS; ++q) {
            const float4 g = gl4[q * 256 + tid];
            float d0 = sv.x - g.x + 1e-6f;
            float d1 = sv.y - g.y + 1e-6f;
            float d2 = sv.z - g.z + 1e-6f;
            float d3 = sv.w - g.w + 1e-6f;
            acc[q] = fmaf(d0, d0, fmaf(d1, d1, fmaf(d2, d2, d3 * d3)));
        }

        // block reduce: warp shfl, fixed-order cross-warp (deterministic)
        #pragma unroll
        for (int q = 0; q < SS; ++q) {
            float v = acc[q];
            #pragma unroll
            for (int off = 16; off > 0; off >>= 1)
                v += __shfl_xor_sync(0xffffffffu, v, off);
            if (lane == 0) s_red[q * 8 + wid] = v;
        }
        __syncthreads();

        if (wid == 0) {
            float tot = 0.0f;
            if (lane < SS) {
                #pragma unroll
                for (int w = 0; w < 8; ++w) tot += s_red[lane * 8 + w];
            }
            if (lane == 0) {
                const int sid = s_sid[s];
                float pos  = 0.0f;
                float minv = 1e30f;   // strict < == argmin first-index tie rule
                float neg  = 0.0f;
                #pragma unroll
                for (int q = 0; q < SS; ++q) {
                    float ds = sqrtf(__shfl_sync(0xffffffffu, tot, q));
                    if (q == sid) pos = ds;
                    bool valid = (s_mask[s * SS + q] != 0) && (q != sid);
                    float m = valid ? ds : 10.0f;          // SENTINEL
                    if (m < minv) { minv = m; neg = ds; }  // carry REAL dist at argmin
                }
                g_margin_part[tt] = fmaxf(pos - neg + 0.5f, 0.0f);
            } else {
                #pragma unroll
                for (int q = 0; q < SS; ++q)
                    (void)__shfl_sync(0xffffffffu, tot, q);
            }
        }
        __syncthreads();   // all reads of buf[s] + s_red complete

        // refill slot s immediately (keeps 4 copies outstanding)
        if (tid == 0) s_tq[s] = atomicAdd(&g_ticket, 1u);
        __syncthreads();
        const unsigned int tn = s_tq[s];
        if (tn < NB) {
            unsigned char* buf = smem + s * ROW_BYTES;
            if (tid == 0) {
                const unsigned int mb = smem_u32(&mbar_p[s]);
                mbar_expect_tx(mb, ROW_BYTES);
                bulk_g2s(smem_u32(buf), sentence + (size_t)tn * HH, SENT_BYTES, mb);
                bulk_g2s(smem_u32(buf) + SENT_BYTES, gloss + (size_t)tn * SS * HH,
                         GLOSS_BYTES, mb);
            }
            if (tid < SS) s_mask[s * SS + tid] = mask[tn * SS + tid];
            if (tid == SS) s_sid[s] = sids[tn];
        }
        __syncthreads();

        s = (s + 1) & (NBUF - 1);
    }

    // ---- completion-counter fused finalize (last block only) ----
    if (tid == 0) {
        __threadfence();
        unsigned int d = atomicAdd(&g_done, 1u);
        *s_last = (d == (unsigned int)(gridDim.x - 1)) ? 1 : 0;
    }
    __syncthreads();
    if (*s_last == 0) return;

    // margin sum, fixed order -> bit-deterministic (reuse buffer 0 as scratch)
    float* sh = reinterpret_cast<float*>(smem);
    float m = 0.0f;
    for (int i = tid; i < NB; i += THREADS) m += g_margin_part[i];
    sh[tid] = m;
    __syncthreads();
    #pragma unroll
    for (int off = THREADS / 2; off > 0; off >>= 1) {
        if (tid < off) sh[tid] += sh[tid + off];
        __syncthreads();
    }
    float margin = sh[0];
    __syncthreads();

    sh[tid] = (tid < ALPHA_CHUNKS) ? g_alpha_part[tid] : 0.0f;
    __syncthreads();
    #pragma unroll
    for (int off = THREADS / 2; off > 0; off >>= 1) {
        if (tid < off) sh[tid] += sh[tid + off];
        __syncthreads();
    }
    float alpha_term = sh[0];

    if (tid == 0) {
        float loss = margin * 0.875f + alpha_term * 0.125f;
        out[0] = loss;
        if (out_size > 1) out[1] = margin;
        if (out_size > 2) out[2] = alpha_term;
        // self-reset for next graph replay
        g_ticket = 0u;
        g_done   = 0u;
    }
}

extern "C" void kernel_launch(void* const* d_in, const int* in_sizes, int n_in,
                              void* d_out, int out_size)
{
    // Identify inputs robustly by element count (all distinct):
    //   sentence  8192*1024    = 8388608  (f32)
    //   all_gloss 8192*10*1024 = 83886080 (f32)
    //   alpha     2700*6*10    = 162000   (f32)
    //   sense_mask 8192*10     = 81920    (i32)
    //   sense_ids 8192         = 8192     (i32)
    const float* sentence = nullptr;
    const float* gloss    = nullptr;
    const float* alpha    = nullptr;
    const int*   mask     = nullptr;
    const int*   sids     = nullptr;
    for (int i = 0; i < n_in; ++i) {
        switch (in_sizes[i]) {
            case 8388608:  sentence = (const float*)d_in[i]; break;
            case 83886080: gloss    = (const float*)d_in[i]; break;
            case 162000:   alpha    = (const float*)d_in[i]; break;
            case 81920:    mask     = (const int*)  d_in[i]; break;
            case 8192:     sids     = (const int*)  d_in[i]; break;
            default: break;
        }
    }

    static int attr_done = 0;
    if (!attr_done) {
        cudaFuncSetAttribute(marginal_loss_fused,
                             cudaFuncAttributeMaxDynamicSharedMemorySize, DYN_SMEM);
        attr_done = 1;
    }

    marginal_loss_fused<<<NBLOCKS, THREADS, DYN_SMEM>>>(
        sentence, gloss, alpha, mask, sids, (float*)d_out, out_size);
}

// round 17
// speedup vs baseline: 3.5308x; 3.5308x over previous
#include <cuda_runtime.h>
#include <cstdint>
#include <math.h>

// Problem shapes (fixed by the reference)
#define NB 8192          // batch
#define SS 10            // senses
#define HH 1024          // hidden
#define THREADS 64       // 2 warps/block
#define WARPS 2
#define NBLOCKS 740      // 5 blocks/SM x 148
#define TMA_BLOCKS 148   // blocks 0..147: one TMA-type block per SM
#define ALPHA_ROWS 16200 // 2700*6
#define ALPHA_CHUNKS 64
#define ALPHA_CHUNK 254
#define NTICKETS (NB + ALPHA_CHUNKS)

// cp.async side
#define NSTAGE 4
#define STAGE_BYTES (11 * 512)                    // 5632
#define CP_BYTES (WARPS * NSTAGE * STAGE_BYTES)   // 45056

// TMA side layout (within same dyn smem)
#define RING_OFF  0          // 4 x 8192 = 32768
#define CHUNK_B   8192       // 2 senses per chunk
#define SENT_OFF  32768      // 4096
#define TCTRL_OFF 36864      // mbar[5], ticket, sid, mask, red
#define SLAST_OFF 45504      // common last-block flag
#define DYN_SMEM  45568      // 5 blocks/SM (5*45568 = 227840 <= smem/SM)

// Scratch (device globals: no allocation anywhere)
__device__ float g_margin_part[NB];
__device__ float g_alpha_part[ALPHA_CHUNKS];
__device__ unsigned int g_ticket;  // zero-init; self-resetting
__device__ unsigned int g_done;    // zero-init; self-resetting

#define CP_ASYNC16(dst_smem, src_gmem) \
    asm volatile("cp.async.cg.shared.global [%0], [%1], 16;" \
                 :: "r"(dst_smem), "l"(src_gmem) : "memory")
#define CP_COMMIT() asm volatile("cp.async.commit_group;" ::: "memory")
#define CP_WAIT3()  asm volatile("cp.async.wait_group 3;" ::: "memory")
#define CP_WAIT0()  asm volatile("cp.async.wait_group 0;" ::: "memory")

__device__ __forceinline__ unsigned int smem_u32(const void* p) {
    return (unsigned int)__cvta_generic_to_shared(p);
}
__device__ __forceinline__ void mbar_init(unsigned int mbar, unsigned int cnt) {
    asm volatile("mbarrier.init.shared.b64 [%0], %1;" :: "r"(mbar), "r"(cnt) : "memory");
}
__device__ __forceinline__ void mbar_expect_tx(unsigned int mbar, unsigned int bytes) {
    asm volatile("mbarrier.arrive.expect_tx.shared.b64 _, [%0], %1;"
                 :: "r"(mbar), "r"(bytes) : "memory");
}
__device__ __forceinline__ void mbar_wait(unsigned int mbar, unsigned int parity) {
    asm volatile(
        "{\n\t"
        ".reg .pred P1;\n\t"
        "WAIT_LOOP_%=:\n\t"
        "mbarrier.try_wait.parity.acquire.cta.shared::cta.b64 P1, [%0], %1, 0x989680;\n\t"
        "@P1 bra.uni WAIT_DONE_%=;\n\t"
        "bra.uni WAIT_LOOP_%=;\n\t"
        "WAIT_DONE_%=:\n\t"
        "}"
        :: "r"(mbar), "r"(parity) : "memory");
}
__device__ __forceinline__ void bulk_g2s(unsigned int dst_smem, const void* src,
                                         unsigned int bytes, unsigned int mbar) {
    asm volatile(
        "cp.async.bulk.shared::cluster.global.mbarrier::complete_tx::bytes "
        "[%0], [%1], %2, [%3];"
        :: "r"(dst_smem), "l"(src), "r"(bytes), "r"(mbar) : "memory");
}

// cp.async stage issue (same-lane staging, R13-proven)
__device__ __forceinline__ void issue_stage(const float* __restrict__ sentence,
                                            const float* __restrict__ gloss,
                                            int b, int j, unsigned int smem_base, int lane)
{
    const float4* s = reinterpret_cast<const float4*>(sentence + (size_t)b * HH)
                      + j * 32 + lane;
    CP_ASYNC16(smem_base + lane * 16, s);
    const float4* g0 = reinterpret_cast<const float4*>(gloss + (size_t)b * SS * HH)
                       + j * 32 + lane;
    #pragma unroll
    for (int l = 0; l < SS; ++l)
        CP_ASYNC16(smem_base + (l + 1) * 512 + lane * 16, g0 + l * 256);
}

// shared alpha-chunk handler (warp-granular, deterministic)
__device__ __forceinline__ void do_alpha_warp(const float* __restrict__ alpha,
                                              int c, int lane)
{
    const int start = c * ALPHA_CHUNK;
    const int end   = min(start + ALPHA_CHUNK, ALPHA_ROWS);
    float part = 0.0f;
    for (int r = start + lane; r < end; r += 32) {
        const float* __restrict__ row = alpha + (size_t)r * 10;
        float s0 = 0.0f, mx = -1e30f;
        #pragma unroll
        for (int k = 0; k < 10; ++k) {
            float v = row[k];
            s0 += v;
            mx = fmaxf(mx, v);
        }
        part += (s0 == 0.0f) ? 0.0f : fabsf(mx - 1.0f);  // row_sum==0 -> 0
    }
    #pragma unroll
    for (int off = 16; off > 0; off >>= 1)
        part += __shfl_xor_sync(0xffffffffu, part, off);
    if (lane == 0) g_alpha_part[c] = part;
}

__global__ __launch_bounds__(THREADS)
void marginal_loss_fused(const float* __restrict__ sentence,
                         const float* __restrict__ gloss,
                         const float* __restrict__ alpha,
                         const int*   __restrict__ mask,
                         const int*   __restrict__ sids,
                         float* __restrict__ out, int out_size)
{
    extern __shared__ __align__(128) unsigned char dyn[];
    const int tid  = threadIdx.x;
    const int lane = tid & 31;
    const int warp = tid >> 5;
    int* s_last = reinterpret_cast<int*>(dyn + SLAST_OFF);

    if (blockIdx.x < TMA_BLOCKS) {
        // ===================== TMA-type block (1 per SM) =====================
        unsigned long long* mb = reinterpret_cast<unsigned long long*>(dyn + TCTRL_OFF);
        unsigned int* s_t = reinterpret_cast<unsigned int*>(dyn + TCTRL_OFF + 64);
        int*   s_sid  = reinterpret_cast<int*>(dyn + TCTRL_OFF + 68);
        int*   s_mask = reinterpret_cast<int*>(dyn + TCTRL_OFF + 72);   // [10]
        float* s_red  = reinterpret_cast<float*>(dyn + TCTRL_OFF + 128); // [10][2]
        const float* sentf  = reinterpret_cast<const float*>(dyn + SENT_OFF);

        int ph0 = 0, ph1 = 0, ph2 = 0, ph3 = 0, ph4 = 0;
        if (tid == 0) {
            #pragma unroll
            for (int k = 0; k < 5; ++k) mbar_init(smem_u32(&mb[k]), 1);
        }
        __syncthreads();

        for (;;) {
            if (tid == 0) *s_t = atomicAdd(&g_ticket, 1u);
            __syncthreads();
            const unsigned int t = *s_t;
            __syncthreads();
            if (t >= NTICKETS) break;

            if (t >= NB) {              // alpha ticket (endgame only)
                if (warp == 0) do_alpha_warp(alpha, (int)(t - NB), lane);
                __syncthreads();
                continue;
            }

            const float* grow = gloss + (size_t)t * SS * HH;
            if (tid == 0) {
                mbar_expect_tx(smem_u32(&mb[4]), 4096);
                bulk_g2s(smem_u32(dyn + SENT_OFF), sentence + (size_t)t * HH,
                         4096, smem_u32(&mb[4]));
                #pragma unroll
                for (int c = 0; c < 4; ++c) {
                    mbar_expect_tx(smem_u32(&mb[c]), CHUNK_B);
                    bulk_g2s(smem_u32(dyn + RING_OFF + c * CHUNK_B),
                             grow + c * 2048, CHUNK_B, smem_u32(&mb[c]));
                }
            }
            if (tid < SS) s_mask[tid] = mask[t * SS + tid];
            if (tid == SS) *s_sid = sids[t];
            __syncthreads();

            mbar_wait(smem_u32(&mb[4]), ph4); ph4 ^= 1;
            const float4* sf4 = reinterpret_cast<const float4*>(sentf);
            float4 sv[4];
            #pragma unroll
            for (int k = 0; k < 4; ++k) sv[k] = sf4[tid + k * 64];

            float acc[SS];
            #pragma unroll
            for (int c = 0; c < 5; ++c) {
                const int slot = c & 3;
                if (slot == 0 && c == 0) { mbar_wait(smem_u32(&mb[0]), ph0); ph0 ^= 1; }
                else if (slot == 1) { mbar_wait(smem_u32(&mb[1]), ph1); ph1 ^= 1; }
                else if (slot == 2) { mbar_wait(smem_u32(&mb[2]), ph2); ph2 ^= 1; }
                else if (slot == 3) { mbar_wait(smem_u32(&mb[3]), ph3); ph3 ^= 1; }
                else { mbar_wait(smem_u32(&mb[0]), ph0); ph0 ^= 1; }   // c==4

                const float4* gp = reinterpret_cast<const float4*>(
                    dyn + RING_OFF + slot * CHUNK_B);
                #pragma unroll
                for (int sl = 0; sl < 2; ++sl) {
                    float a = 0.0f;
                    #pragma unroll
                    for (int k = 0; k < 4; ++k) {
                        const float4 g = gp[sl * 256 + tid + k * 64];
                        const float4 s = sv[k];
                        float d0 = s.x - g.x + 1e-6f;
                        float d1 = s.y - g.y + 1e-6f;
                        float d2 = s.z - g.z + 1e-6f;
                        float d3 = s.w - g.w + 1e-6f;
                        a = fmaf(d0, d0, a); a = fmaf(d1, d1, a);
                        a = fmaf(d2, d2, a); a = fmaf(d3, d3, a);
                    }
                    acc[2 * c + sl] = a;
                }

                if (c == 0) {
                    __syncthreads();          // all reads of slot0 done
                    if (tid == 0) {           // refill slot0 with chunk 4
                        mbar_expect_tx(smem_u32(&mb[0]), CHUNK_B);
                        bulk_g2s(smem_u32(dyn + RING_OFF),
                                 grow + 4 * 2048, CHUNK_B, smem_u32(&mb[0]));
                    }
                }
            }

            // block reduce (2 warps): warp shfl, fixed-order cross-warp
            #pragma unroll
            for (int q = 0; q < SS; ++q) {
                float v = acc[q];
                #pragma unroll
                for (int off = 16; off > 0; off >>= 1)
                    v += __shfl_xor_sync(0xffffffffu, v, off);
                if (lane == 0) s_red[q * 2 + warp] = v;
            }
            __syncthreads();

            if (warp == 0) {
                float tot = 0.0f;
                if (lane < SS) tot = s_red[lane * 2 + 0] + s_red[lane * 2 + 1];
                if (lane == 0) {
                    const int sid = *s_sid;
                    float pos  = 0.0f;
                    float minv = 1e30f;   // strict < == argmin first-index tie rule
                    float neg  = 0.0f;
                    #pragma unroll
                    for (int q = 0; q < SS; ++q) {
                        float ds = sqrtf(__shfl_sync(0xffffffffu, tot, q));
                        if (q == sid) pos = ds;
                        bool valid = (s_mask[q] != 0) && (q != sid);
                        float m = valid ? ds : 10.0f;          // SENTINEL
                        if (m < minv) { minv = m; neg = ds; }  // REAL dist at argmin
                    }
                    g_margin_part[t] = fmaxf(pos - neg + 0.5f, 0.0f);
                } else {
                    #pragma unroll
                    for (int q = 0; q < SS; ++q)
                        (void)__shfl_sync(0xffffffffu, tot, q);
                }
            }
            __syncthreads();
        }
        // every issued copy was waited -> nothing outstanding
    } else {
        // ===================== cp.async-type block (R13) =====================
        const unsigned int wbase = smem_u32(dyn) + warp * (NSTAGE * STAGE_BYTES);

        unsigned int t;
        if (lane == 0) t = atomicAdd(&g_ticket, 1u);
        t = __shfl_sync(0xffffffffu, t, 0);
        bool primed = false;

        while (t < NTICKETS) {
            if (t < NB) {
                const int b = (int)t;
                if (!primed) {
                    #pragma unroll
                    for (int k = 0; k < 3; ++k) {
                        issue_stage(sentence, gloss, b, k, wbase + k * STAGE_BYTES, lane);
                        CP_COMMIT();
                    }
                }

                float acc[SS];
                #pragma unroll
                for (int s = 0; s < SS; ++s) acc[s] = 0.0f;

                unsigned int tn = NTICKETS;

                #pragma unroll
                for (int j = 0; j < 8; ++j) {
                    const int pj = j + 3;
                    if (pj < 8) {
                        issue_stage(sentence, gloss, b, pj,
                                    wbase + (pj & 3) * STAGE_BYTES, lane);
                    } else {
                        const int k = pj - 8;
                        if (k == 0) {
                            if (lane == 0) tn = atomicAdd(&g_ticket, 1u);
                            tn = __shfl_sync(0xffffffffu, tn, 0);
                        }
                        if (tn < NB)
                            issue_stage(sentence, gloss, (int)tn, k,
                                        wbase + (k & 3) * STAGE_BYTES, lane);
                    }
                    CP_COMMIT();
                    CP_WAIT3();

                    const float4* p = reinterpret_cast<const float4*>(
                        dyn + warp * (NSTAGE * STAGE_BYTES) + (j & 3) * STAGE_BYTES);
                    const float4 sv = p[lane];
                    #pragma unroll
                    for (int s = 0; s < SS; ++s) {
                        float4 g = p[(s + 1) * 32 + lane];
                        float d0 = sv.x - g.x + 1e-6f;
                        float d1 = sv.y - g.y + 1e-6f;
                        float d2 = sv.z - g.z + 1e-6f;
                        float d3 = sv.w - g.w + 1e-6f;
                        float a = acc[s];
                        a = fmaf(d0, d0, a); a = fmaf(d1, d1, a);
                        a = fmaf(d2, d2, a); a = fmaf(d3, d3, a);
                        acc[s] = a;
                    }
                }

                #pragma unroll
                for (int s = 0; s < SS; ++s) {
                    float v = acc[s];
                    #pragma unroll
                    for (int off = 16; off > 0; off >>= 1)
                        v += __shfl_xor_sync(0xffffffffu, v, off);
                    acc[s] = v;
                }

                if (lane == 0) {
                    const int sid = sids[b];
                    float pos  = 0.0f;
                    float minv = 1e30f;
                    float neg  = 0.0f;
                    #pragma unroll
                    for (int s = 0; s < SS; ++s) {
                        float ds = sqrtf(acc[s]);
                        if (s == sid) pos = ds;
                        bool valid = (mask[b * SS + s] != 0) && (s != sid);
                        float m = valid ? ds : 10.0f;
                        if (m < minv) { minv = m; neg = ds; }
                    }
                    g_margin_part[b] = fmaxf(pos - neg + 0.5f, 0.0f);
                }

                primed = (tn < NB);
                t = tn;
            } else {
                do_alpha_warp(alpha, (int)(t - NB), lane);
                if (lane == 0) t = atomicAdd(&g_ticket, 1u);
                t = __shfl_sync(0xffffffffu, t, 0);
                primed = false;
            }
        }
        CP_WAIT0();   // drain before finalize/exit
    }

    // ---- completion-counter fused finalize (last block only) ----
    __syncthreads();
    if (tid == 0) {
        __threadfence();
        unsigned int d = atomicAdd(&g_done, 1u);
        *s_last = (d == (unsigned int)(gridDim.x - 1)) ? 1 : 0;
    }
    __syncthreads();
    if (*s_last == 0) return;

    float* sh = reinterpret_cast<float*>(dyn);   // both pipelines drained

    float m = 0.0f;
    for (int i = tid; i < NB; i += THREADS) m += g_margin_part[i];
    sh[tid] = m;
    __syncthreads();
    #pragma unroll
    for (int off = THREADS / 2; off > 0; off >>= 1) {
        if (tid < off) sh[tid] += sh[tid + off];
        __syncthreads();
    }
    float margin = sh[0];
    __syncthreads();

    sh[tid] = (tid < ALPHA_CHUNKS) ? g_alpha_part[tid] : 0.0f;
    __syncthreads();
    #pragma unroll
    for (int off = THREADS / 2; off > 0; off >>= 1) {
        if (tid < off) sh[tid] += sh[tid + off];
        __syncthreads();
    }
    float alpha_term = sh[0];

    if (tid == 0) {
        float loss = margin * 0.875f + alpha_term * 0.125f;
        out[0] = loss;
        if (out_size > 1) out[1] = margin;
        if (out_size > 2) out[2] = alpha_term;
        g_ticket = 0u;
        g_done   = 0u;
    }
}

extern "C" void kernel_launch(void* const* d_in, const int* in_sizes, int n_in,
                              void* d_out, int out_size)
{
    // Inputs identified by element count (all distinct)
    const float* sentence = nullptr;
    const float* gloss    = nullptr;
    const float* alpha    = nullptr;
    const int*   mask     = nullptr;
    const int*   sids     = nullptr;
    for (int i = 0; i < n_in; ++i) {
        switch (in_sizes[i]) {
            case 8388608:  sentence = (const float*)d_in[i]; break;
            case 83886080: gloss    = (const float*)d_in[i]; break;
            case 162000:   alpha    = (const float*)d_in[i]; break;
            case 81920:    mask     = (const int*)  d_in[i]; break;
            case 8192:     sids     = (const int*)  d_in[i]; break;
            default: break;
        }
    }

    static int attr_done = 0;
    if (!attr_done) {
        cudaFuncSetAttribute(marginal_loss_fused,
                             cudaFuncAttributeMaxDynamicSharedMemorySize, DYN_SMEM);
        attr_done = 1;
    }

    marginal_loss_fused<<<NBLOCKS, THREADS, DYN_SMEM>>>(
        sentence, gloss, alpha, mask, sids, (float*)d_out, out_size);
}